// round 14
// baseline (speedup 1.0000x reference)
#include <cuda_runtime.h>
#include <cuda_bf16.h>
#include <stdint.h>
#include <math.h>

typedef __nv_bfloat16 bf16;

#define S_LEN 128
#define BATCH 64
#define T_LEN 64
#define EMBD  256
#define HID   512
#define DHID  1024
#define VOC   32000

// ---------------------------------------------------------------------------
// Device scratch
// ---------------------------------------------------------------------------
__device__ bf16  g_we0_ih[2][2048 * 256];
__device__ bf16  g_we0_hh[2][2048 * 512];
__device__ float g_be0[2][2048];
__device__ bf16  g_we1_ih[2][2048 * 1024];
__device__ bf16  g_we1_hh[2][2048 * 512];
__device__ float g_be1[2][2048];
__device__ bf16  g_wd0_ih[4096 * 256];
__device__ bf16  g_wd0_hh[4096 * 1024];
__device__ float g_bd0[4096];
__device__ bf16  g_wd1_ih[4096 * 1024];
__device__ bf16  g_wd1_hh[4096 * 1024];
__device__ float g_bd1[4096];
__device__ bf16  g_wout[(size_t)VOC * 1024];

__device__ bf16  g_xsrc[8192 * 256];
__device__ bf16  g_xdec[4096 * 256];
__device__ bf16  g_ya[8192 * 1024];
__device__ bf16  g_yda[4096 * 1024];
__device__ bf16  g_ydb[4096 * 1024];
__device__ float g_xw[2][8192 * 2048];    // enc xw per dir; dec1 reuses [0]
__device__ float g_xw2[4096 * 4096];      // dec0 xw (computed early)
__device__ bf16  g_hbuf[2][2][64 * 1024];
__device__ float g_cbuf[2][64 * 1024];
__device__ bf16  g_dech0[2][64 * 1024];
__device__ float g_decc0[2][64 * 1024];

// ---------------------------------------------------------------------------
// Helpers
// ---------------------------------------------------------------------------
__device__ __forceinline__ float sigf(float x) { return 1.f / (1.f + expf(-x)); }

__device__ __forceinline__ void mma16816(float* c, uint32_t a0, uint32_t a1, uint32_t a2, uint32_t a3,
                                         uint32_t b0, uint32_t b1) {
    asm volatile(
        "mma.sync.aligned.m16n8k16.row.col.f32.bf16.bf16.f32 "
        "{%0,%1,%2,%3},{%4,%5,%6,%7},{%8,%9},{%0,%1,%2,%3};"
        : "+f"(c[0]), "+f"(c[1]), "+f"(c[2]), "+f"(c[3])
        : "r"(a0), "r"(a1), "r"(a2), "r"(a3), "r"(b0), "r"(b1));
}

__device__ __forceinline__ void cp16(void* smem, const void* gmem) {
    uint32_t s = (uint32_t)__cvta_generic_to_shared(smem);
    asm volatile("cp.async.cg.shared.global [%0], [%1], 16;\n" ::"r"(s), "l"(gmem));
}
__device__ __forceinline__ void cp_commit() { asm volatile("cp.async.commit_group;\n"); }
template <int N>
__device__ __forceinline__ void cp_wait() { asm volatile("cp.async.wait_group %0;\n" ::"n"(N)); }

// ---------------------------------------------------------------------------
// Fused weight conversion (one launch): gate-interleave permutation + biases
// row r (gate = r/H, unit j = r%H)  ->  permuted row 4*j + gate
// ---------------------------------------------------------------------------
struct PermJob { const float* src; bf16* dst; int H, K, n; };
struct BiasJob { const float* bih; const float* bhh; float* dst; int H, n; };
struct ConvArgs { PermJob p[12]; BiasJob b[6]; };

__global__ void conv_all(ConvArgs a) {
    int g0 = blockIdx.x * blockDim.x + threadIdx.x;
    int gs = gridDim.x * blockDim.x;
#pragma unroll 1
    for (int j = 0; j < 12; j++) {
        const float* src = a.p[j].src;
        bf16* dst = a.p[j].dst;
        int H = a.p[j].H, K = a.p[j].K, n = a.p[j].n;
        for (int idx = g0; idx < n; idx += gs) {
            int r = idx / K, k = idx - r * K;
            int gate = r / H, jj = r - gate * H;
            dst[(size_t)(jj * 4 + gate) * K + k] = __float2bfloat16(src[idx]);
        }
    }
#pragma unroll 1
    for (int j = 0; j < 6; j++) {
        const float* bih = a.b[j].bih;
        const float* bhh = a.b[j].bhh;
        float* dst = a.b[j].dst;
        int H = a.b[j].H, n = a.b[j].n;
        for (int r = g0; r < n; r += gs) {
            int gate = r / H, jj = r - gate * H;
            dst[jj * 4 + gate] = bih[r] + bhh[r];
        }
    }
}

__global__ void conv_wout(const float* __restrict__ src, bf16* __restrict__ dst, size_t n) {
    for (size_t i = blockIdx.x * (size_t)blockDim.x + threadIdx.x; i < n; i += (size_t)gridDim.x * blockDim.x)
        dst[i] = __float2bfloat16(src[i]);
}

// ---------------------------------------------------------------------------
// Fused embedding gathers (source + decoder inputs)
// ---------------------------------------------------------------------------
__global__ void embed_all(const int* __restrict__ sent, const int* __restrict__ targ,
                          const float* __restrict__ emb, bf16* __restrict__ xs, bf16* __restrict__ xd) {
    int idx = blockIdx.x * blockDim.x + threadIdx.x;
    const int NS = 8192 * 256;
    const int ND = 4096 * 256;
    if (idx < NS) {
        int row = idx >> 8, e = idx & 255;
        xs[idx] = __float2bfloat16(emb[(size_t)sent[row] * EMBD + e]);
    } else if (idx < NS + ND) {
        int i2 = idx - NS;
        int row = i2 >> 8, e = i2 & 255;
        int t = row >> 6, b = row & 63;
        int tok = (t == 0) ? sent[(S_LEN - 1) * BATCH + b] : targ[(t - 1) * BATCH + b];
        xd[i2] = __float2bfloat16(emb[(size_t)tok * EMBD + e]);
    }
}

// ---------------------------------------------------------------------------
// Big GEMM: C[M][N] f32 = A(bf16 MxK rowmaj) @ B(bf16 NxK rowmaj)^T + bias[N]
// 128x128x32 tiles, 256 threads, 4-stage cp.async pipeline, ONE sync per tile.
// grid = (M/128, N/128): consecutive CTAs share the same B tile (L2 reuse).
// Dynamic smem: 4*2*128*40*2 = 80KB.
// ---------------------------------------------------------------------------
#define GST 4
#define GPITCH 40
__global__ __launch_bounds__(256) void gemm_bias(const bf16* __restrict__ A, const bf16* __restrict__ B,
                                                 const float* __restrict__ bias, float* __restrict__ C,
                                                 int M, int N, int K) {
    extern __shared__ bf16 gsm[];
    bf16(*As)[128][GPITCH] = (bf16(*)[128][GPITCH])gsm;
    bf16(*Bs)[128][GPITCH] = (bf16(*)[128][GPITCH])(gsm + GST * 128 * GPITCH);
    int tid = threadIdx.x;
    int m0 = blockIdx.x * 128, n0 = blockIdx.y * 128;
    int warp = tid >> 5, lane = tid & 31, g = lane >> 2, tg = lane & 3;
    int wm = warp >> 1, wn = warp & 1;
    float acc[2][8][4];
#pragma unroll
    for (int a = 0; a < 2; a++)
#pragma unroll
        for (int b = 0; b < 8; b++)
#pragma unroll
            for (int c = 0; c < 4; c++) acc[a][b][c] = 0.f;

    int lrow = tid >> 2, lq = tid & 3;
    int KT = K / 32;

    auto load_tile = [&](int t) {
        int st = t & 3, k0 = t * 32;
        const bf16* Ap = A + (size_t)(m0 + lrow) * K + k0 + lq * 8;
        const bf16* Bp = B + (size_t)(n0 + lrow) * K + k0 + lq * 8;
        cp16(&As[st][lrow][lq * 8], Ap);
        cp16(&As[st][lrow + 64][lq * 8], Ap + (size_t)64 * K);
        cp16(&Bs[st][lrow][lq * 8], Bp);
        cp16(&Bs[st][lrow + 64][lq * 8], Bp + (size_t)64 * K);
    };

    // prologue: exactly GST-1 committed groups (pad with empty commits if KT small)
    int npre = KT < (GST - 1) ? KT : (GST - 1);
    for (int t = 0; t < npre; t++) {
        load_tile(t);
        cp_commit();
    }
    for (int t = npre; t < GST - 1; t++) cp_commit();

    for (int kt = 0; kt < KT; kt++) {
        cp_wait<GST - 2>();   // tile kt resident
        __syncthreads();      // all warps done with stage (kt-1)%4; data visible
        if (kt + GST - 1 < KT) load_tile(kt + GST - 1);
        cp_commit();          // one group per iteration (possibly empty)
        int cur = kt & 3;
#pragma unroll
        for (int kk = 0; kk < 2; kk++) {
            uint32_t afr[2][4];
#pragma unroll
            for (int mi = 0; mi < 2; mi++) {
                int r = wm * 32 + mi * 16;
                afr[mi][0] = *(uint32_t*)&As[cur][r + g][kk * 16 + tg * 2];
                afr[mi][1] = *(uint32_t*)&As[cur][r + g + 8][kk * 16 + tg * 2];
                afr[mi][2] = *(uint32_t*)&As[cur][r + g][kk * 16 + tg * 2 + 8];
                afr[mi][3] = *(uint32_t*)&As[cur][r + g + 8][kk * 16 + tg * 2 + 8];
            }
#pragma unroll
            for (int ni = 0; ni < 8; ni++) {
                int cb = wn * 64 + ni * 8;
                uint32_t b0 = *(uint32_t*)&Bs[cur][cb + g][kk * 16 + tg * 2];
                uint32_t b1 = *(uint32_t*)&Bs[cur][cb + g][kk * 16 + tg * 2 + 8];
                mma16816(acc[0][ni], afr[0][0], afr[0][1], afr[0][2], afr[0][3], b0, b1);
                mma16816(acc[1][ni], afr[1][0], afr[1][1], afr[1][2], afr[1][3], b0, b1);
            }
        }
    }
#pragma unroll
    for (int mi = 0; mi < 2; mi++) {
#pragma unroll
        for (int ni = 0; ni < 8; ni++) {
            int r = m0 + wm * 32 + mi * 16 + g;
            int c = n0 + wn * 64 + ni * 8 + tg * 2;
            float bv0 = bias[c], bv1 = bias[c + 1];
            float2 v0 = make_float2(acc[mi][ni][0] + bv0, acc[mi][ni][1] + bv1);
            float2 v1 = make_float2(acc[mi][ni][2] + bv0, acc[mi][ni][3] + bv1);
            *(float2*)&C[(size_t)r * N + c] = v0;
            *(float2*)&C[(size_t)(r + 8) * N + c] = v1;
        }
    }
}

// ---------------------------------------------------------------------------
// Fused LSTM step (per-step launch): gates = xw[t] + h_prev @ Whh^T (gate-
// interleaved), cell nonlinearity in epilogue. cp.async double buffered.
// grid = (N/64, 1, ndirs), block = 128.
// ---------------------------------------------------------------------------
struct StepArgs {
    const float* xw[2];
    const bf16* hprev[2];
    bf16* hnew[2];
    const float* cin[2];
    float* cout[2];
    const bf16* Whh[2];
    bf16* y;
    int y_off[2];
    int t[2];
    int K;  // hidden dim (512 or 1024)
    int N;  // 4*H
    bf16* exp_h;
    float* exp_c;
    int exp_off[2];
    int do_export;
};

__global__ __launch_bounds__(128) void lstm_step(StepArgs p) {
    __shared__ bf16 As[2][64][GPITCH];
    __shared__ bf16 Bs[2][64][GPITCH];
    int dir = blockIdx.z;
    int tid = threadIdx.x, warp = tid >> 5, lane = tid & 31, g = lane >> 2, tg = lane & 3;
    int nb = blockIdx.x * 64;
    int N = p.N, K = p.K;
    float acc[8][4];
#pragma unroll
    for (int a = 0; a < 8; a++)
#pragma unroll
        for (int b = 0; b < 4; b++) acc[a][b] = 0.f;

    const bf16* hp = p.hprev[dir];
    if (hp) {
        const bf16* W = p.Whh[dir] + (size_t)nb * K;
        int lr = tid >> 2, lq = tid & 3;
        int KT = K / 32;
        {
            const bf16* Ap = hp + (size_t)lr * K + lq * 8;
            const bf16* Bp = W + (size_t)lr * K + lq * 8;
            cp16(&As[0][lr][lq * 8], Ap);
            cp16(&As[0][lr + 32][lq * 8], Ap + (size_t)32 * K);
            cp16(&Bs[0][lr][lq * 8], Bp);
            cp16(&Bs[0][lr + 32][lq * 8], Bp + (size_t)32 * K);
            cp_commit();
        }
        for (int kt = 0; kt < KT; kt++) {
            int cur = kt & 1;
            if (kt + 1 < KT) {
                int k0 = (kt + 1) * 32;
                const bf16* Ap = hp + (size_t)lr * K + k0 + lq * 8;
                const bf16* Bp = W + (size_t)lr * K + k0 + lq * 8;
                cp16(&As[cur ^ 1][lr][lq * 8], Ap);
                cp16(&As[cur ^ 1][lr + 32][lq * 8], Ap + (size_t)32 * K);
                cp16(&Bs[cur ^ 1][lr][lq * 8], Bp);
                cp16(&Bs[cur ^ 1][lr + 32][lq * 8], Bp + (size_t)32 * K);
                cp_commit();
                cp_wait<1>();
            } else {
                cp_wait<0>();
            }
            __syncthreads();
#pragma unroll
            for (int kk = 0; kk < 2; kk++) {
                int r = warp * 16;
                uint32_t a0 = *(uint32_t*)&As[cur][r + g][kk * 16 + tg * 2];
                uint32_t a1 = *(uint32_t*)&As[cur][r + g + 8][kk * 16 + tg * 2];
                uint32_t a2 = *(uint32_t*)&As[cur][r + g][kk * 16 + tg * 2 + 8];
                uint32_t a3 = *(uint32_t*)&As[cur][r + g + 8][kk * 16 + tg * 2 + 8];
#pragma unroll
                for (int ni = 0; ni < 8; ni++) {
                    uint32_t b0 = *(uint32_t*)&Bs[cur][ni * 8 + g][kk * 16 + tg * 2];
                    uint32_t b1 = *(uint32_t*)&Bs[cur][ni * 8 + g][kk * 16 + tg * 2 + 8];
                    mma16816(acc[ni], a0, a1, a2, a3, b0, b1);
                }
            }
            __syncthreads();
        }
    }
    // add precomputed input projection (+ folded biases)
    const float* xw = p.xw[dir] + (size_t)p.t[dir] * 64 * N;
    int r0 = warp * 16 + g;
#pragma unroll
    for (int ni = 0; ni < 8; ni++) {
        int c = nb + ni * 8 + tg * 2;
        float2 x0 = *(const float2*)&xw[(size_t)r0 * N + c];
        float2 x1 = *(const float2*)&xw[(size_t)(r0 + 8) * N + c];
        acc[ni][0] += x0.x;
        acc[ni][1] += x0.y;
        acc[ni][2] += x1.x;
        acc[ni][3] += x1.y;
    }
    // LSTM cell: cols 4j..4j+3 = (i,f,g,o); lane pairs (tg, tg^1) share a unit
    int hd = N >> 2;
#pragma unroll
    for (int ni = 0; ni < 8; ni++) {
#pragma unroll
        for (int h2 = 0; h2 < 2; h2++) {
            float v0 = acc[ni][2 * h2], v1 = acc[ni][2 * h2 + 1];
            float w0 = __shfl_xor_sync(0xffffffffu, v0, 1);
            float w1 = __shfl_xor_sync(0xffffffffu, v1, 1);
            if ((tg & 1) == 0) {
                float iv = v0, fv = v1, gv = w0, ov = w1;
                int j = blockIdx.x * 16 + ni * 2 + (tg >> 1);
                int b = warp * 16 + g + h2 * 8;
                size_t ci = (size_t)b * hd + j;
                float cold = p.cin[dir] ? p.cin[dir][ci] : 0.f;
                float cn = sigf(fv) * cold + sigf(iv) * tanhf(gv);
                float hn = sigf(ov) * tanhf(cn);
                p.cout[dir][ci] = cn;
                p.hnew[dir][ci] = __float2bfloat16(hn);
                if (p.y)
                    p.y[(size_t)(p.t[dir] * 64 + b) * 1024 + p.y_off[dir] + j] = __float2bfloat16(hn);
                if (p.do_export) {
                    size_t ei = (size_t)b * 1024 + p.exp_off[dir] + j;
                    p.exp_h[ei] = __float2bfloat16(hn);
                    p.exp_c[ei] = cn;
                }
            }
        }
    }
}

// ---------------------------------------------------------------------------
// In-place log_softmax over rows of 32000 f32 (online max/sum: 2 passes)
// ---------------------------------------------------------------------------
__global__ void logsoftmax_kernel(float* __restrict__ out) {
    float* x = out + (size_t)blockIdx.x * VOC;
    __shared__ float redm[256];
    __shared__ float reds[256];
    int tid = threadIdx.x;
    const float4* x4 = (const float4*)x;
    float m = -1e30f, ssum = 0.f;
    for (int i = tid; i < VOC / 4; i += 256) {
        float4 v = x4[i];
        float vm = fmaxf(fmaxf(v.x, v.y), fmaxf(v.z, v.w));
        if (vm > m) {
            ssum = ssum * expf(m - vm);
            m = vm;
        }
        ssum += expf(v.x - m) + expf(v.y - m) + expf(v.z - m) + expf(v.w - m);
    }
    redm[tid] = m;
    reds[tid] = ssum;
    __syncthreads();
    for (int s = 128; s > 0; s >>= 1) {
        if (tid < s) {
            float m2 = redm[tid + s], s2 = reds[tid + s];
            float m1 = redm[tid], s1 = reds[tid];
            float M = fmaxf(m1, m2);
            redm[tid] = M;
            reds[tid] = s1 * expf(m1 - M) + s2 * expf(m2 - M);
        }
        __syncthreads();
    }
    float lse = redm[0] + logf(reds[0]);
    __syncthreads();
    float4* xw4 = (float4*)x;
    for (int i = tid; i < VOC / 4; i += 256) {
        float4 v = xw4[i];
        v.x -= lse; v.y -= lse; v.z -= lse; v.w -= lse;
        xw4[i] = v;
    }
}

// ---------------------------------------------------------------------------
// Host
// ---------------------------------------------------------------------------
static void* symaddr(const void* sym) {
    void* p = nullptr;
    cudaGetSymbolAddress(&p, sym);
    return p;
}

extern "C" void kernel_launch(void* const* d_in, const int* in_sizes, int n_in,
                              void* d_out, int out_size) {
    cudaStream_t s = 0;
    const int* sent = (const int*)d_in[0];
    const int* targ = (const int*)d_in[1];
    const float* emb = (const float*)d_in[2];
    const float* e0_Wih = (const float*)d_in[3];
    const float* e0_Whh = (const float*)d_in[4];
    const float* e0_bih = (const float*)d_in[5];
    const float* e0_bhh = (const float*)d_in[6];
    const float* e1_Wih = (const float*)d_in[7];
    const float* e1_Whh = (const float*)d_in[8];
    const float* e1_bih = (const float*)d_in[9];
    const float* e1_bhh = (const float*)d_in[10];
    const float* d0_Wih = (const float*)d_in[11];
    const float* d0_Whh = (const float*)d_in[12];
    const float* d0_bih = (const float*)d_in[13];
    const float* d0_bhh = (const float*)d_in[14];
    const float* d1_Wih = (const float*)d_in[15];
    const float* d1_Whh = (const float*)d_in[16];
    const float* d1_bih = (const float*)d_in[17];
    const float* d1_bhh = (const float*)d_in[18];
    const float* W_out = (const float*)d_in[19];
    const float* b_out = (const float*)d_in[20];

    bf16* we0_ih = (bf16*)symaddr(g_we0_ih);
    bf16* we0_hh = (bf16*)symaddr(g_we0_hh);
    float* be0 = (float*)symaddr(g_be0);
    bf16* we1_ih = (bf16*)symaddr(g_we1_ih);
    bf16* we1_hh = (bf16*)symaddr(g_we1_hh);
    float* be1 = (float*)symaddr(g_be1);
    bf16* wd0_ih = (bf16*)symaddr(g_wd0_ih);
    bf16* wd0_hh = (bf16*)symaddr(g_wd0_hh);
    float* bd0 = (float*)symaddr(g_bd0);
    bf16* wd1_ih = (bf16*)symaddr(g_wd1_ih);
    bf16* wd1_hh = (bf16*)symaddr(g_wd1_hh);
    float* bd1 = (float*)symaddr(g_bd1);
    bf16* wout = (bf16*)symaddr(g_wout);
    bf16* xsrc = (bf16*)symaddr(g_xsrc);
    bf16* xdec = (bf16*)symaddr(g_xdec);
    bf16* ya = (bf16*)symaddr(g_ya);
    bf16* yda = (bf16*)symaddr(g_yda);
    bf16* ydb = (bf16*)symaddr(g_ydb);
    float* xwb = (float*)symaddr(g_xw);
    float* xw2 = (float*)symaddr(g_xw2);
    bf16* hbuf = (bf16*)symaddr(g_hbuf);
    float* cbuf = (float*)symaddr(g_cbuf);
    bf16* dech0 = (bf16*)symaddr(g_dech0);
    float* decc0 = (float*)symaddr(g_decc0);

    const size_t XW_STRIDE = (size_t)8192 * 2048;
    const size_t HB = (size_t)64 * 1024;
    float* xw0 = xwb;
    float* xw1 = xwb + XW_STRIDE;

    const int GEMM_SMEM = GST * 2 * 128 * GPITCH * (int)sizeof(bf16);  // 80KB
    cudaFuncSetAttribute(gemm_bias, cudaFuncAttributeMaxDynamicSharedMemorySize, GEMM_SMEM);

    // ---- [0] fused weight conversion ----
    {
        ConvArgs a;
        int j = 0;
        auto addP = [&](const float* src, bf16* dst, int H, int K) {
            a.p[j].src = src; a.p[j].dst = dst; a.p[j].H = H; a.p[j].K = K; a.p[j].n = 4 * H * K; j++;
        };
        for (int d = 0; d < 2; d++) {
            addP(e0_Wih + (size_t)d * 2048 * 256, we0_ih + (size_t)d * 2048 * 256, HID, 256);
            addP(e0_Whh + (size_t)d * 2048 * 512, we0_hh + (size_t)d * 2048 * 512, HID, 512);
            addP(e1_Wih + (size_t)d * 2048 * 1024, we1_ih + (size_t)d * 2048 * 1024, HID, 1024);
            addP(e1_Whh + (size_t)d * 2048 * 512, we1_hh + (size_t)d * 2048 * 512, HID, 512);
        }
        addP(d0_Wih, wd0_ih, DHID, 256);
        addP(d0_Whh, wd0_hh, DHID, 1024);
        addP(d1_Wih, wd1_ih, DHID, 1024);
        addP(d1_Whh, wd1_hh, DHID, 1024);
        int k = 0;
        auto addB = [&](const float* bih, const float* bhh, float* dst, int H) {
            a.b[k].bih = bih; a.b[k].bhh = bhh; a.b[k].dst = dst; a.b[k].H = H; a.b[k].n = 4 * H; k++;
        };
        for (int d = 0; d < 2; d++) {
            addB(e0_bih + d * 2048, e0_bhh + d * 2048, be0 + d * 2048, HID);
            addB(e1_bih + d * 2048, e1_bhh + d * 2048, be1 + d * 2048, HID);
        }
        addB(d0_bih, d0_bhh, bd0, DHID);
        addB(d1_bih, d1_bhh, bd1, DHID);
        conv_all<<<1024, 256, 0, s>>>(a);
    }
    // ---- [1] W_out conversion, [2] embeddings ----
    conv_wout<<<2048, 256, 0, s>>>(W_out, wout, (size_t)VOC * 1024);
    embed_all<<<((8192 + 4096) * 256 + 255) / 256, 256, 0, s>>>(sent, targ, emb, xsrc, xdec);

    auto gemm = [&](const bf16* A, const bf16* B, const float* bias, float* C, int M, int N, int K) {
        dim3 gr(M / 128, N / 128);
        gemm_bias<<<gr, 256, GEMM_SMEM, s>>>(A, B, bias, C, M, N, K);
    };

    auto enc_layer = [&](const bf16* Whh_base, bf16* yout, bf16* exph, float* expc) {
        for (int i = 0; i < S_LEN; i++) {
            StepArgs a = {};
            a.N = 2048;
            a.K = HID;
            a.xw[0] = xw0;
            a.xw[1] = xw1;
            a.Whh[0] = Whh_base;
            a.Whh[1] = Whh_base + (size_t)2048 * 512;
            a.t[0] = i;
            a.t[1] = S_LEN - 1 - i;
            int pi = i & 1, po = pi ^ 1;
            for (int d = 0; d < 2; d++) {
                a.hprev[d] = i ? hbuf + ((size_t)pi * 2 + d) * HB : nullptr;
                a.hnew[d] = hbuf + ((size_t)po * 2 + d) * HB;
                a.cin[d] = i ? cbuf + (size_t)d * HB : nullptr;
                a.cout[d] = cbuf + (size_t)d * HB;
            }
            a.y = yout;
            a.y_off[0] = 0;
            a.y_off[1] = 512;
            a.do_export = (i == S_LEN - 1);
            a.exp_h = exph;
            a.exp_c = expc;
            a.exp_off[0] = 0;
            a.exp_off[1] = 512;
            lstm_step<<<dim3(2048 / 64, 1, 2), 128, 0, s>>>(a);
        }
    };
    auto dec_layer = [&](const float* xw, const bf16* Whh, const bf16* h0, const float* c0, bf16* yout) {
        for (int i = 0; i < T_LEN; i++) {
            StepArgs a = {};
            a.N = 4096;
            a.K = DHID;
            a.xw[0] = xw;
            a.Whh[0] = Whh;
            a.t[0] = i;
            int pi = i & 1, po = pi ^ 1;
            a.hprev[0] = i ? hbuf + (size_t)pi * 2 * HB : h0;
            a.hnew[0] = hbuf + (size_t)po * 2 * HB;
            a.cin[0] = i ? cbuf : c0;
            a.cout[0] = cbuf;
            a.y = yout;
            a.y_off[0] = 0;
            lstm_step<<<dim3(4096 / 64, 1, 1), 128, 0, s>>>(a);
        }
    };

    // [3],[4] enc0 xw; [5] dec0 xw (own buffer, profiler target)
    for (int d = 0; d < 2; d++)
        gemm(xsrc, we0_ih + (size_t)d * 2048 * 256, be0 + d * 2048, (d ? xw1 : xw0), 8192, 2048, 256);
    gemm(xdec, wd0_ih, bd0, xw2, 4096, 4096, 256);
    // encoder layer 0 recurrence
    enc_layer(we0_hh, ya, dech0, decc0);
    // encoder layer 1
    for (int d = 0; d < 2; d++)
        gemm(ya, we1_ih + (size_t)d * 2048 * 1024, be1 + d * 2048, (d ? xw1 : xw0), 8192, 2048, 1024);
    enc_layer(we1_hh, nullptr, dech0 + HB, decc0 + HB);
    // decoder layer 0 (xw precomputed in xw2)
    dec_layer(xw2, wd0_hh, dech0, decc0, yda);
    // decoder layer 1
    gemm(yda, wd1_ih, bd1, xw0, 4096, 4096, 1024);
    dec_layer(xw0, wd1_hh, dech0 + HB, decc0 + HB, ydb);

    // output projection + log_softmax
    gemm(ydb, wout, b_out, (float*)d_out, 4096, VOC, 1024);
    logsoftmax_kernel<<<4096, 256, 0, s>>>((float*)d_out);
}